// round 14
// baseline (speedup 1.0000x reference)
#include <cuda_runtime.h>
#include <cuda_fp16.h>
#include <cstdint>

#define NN    8192
#define DIN   512
#define DOUT  512

// ---------------- helpers ----------------
__device__ __forceinline__ uint32_t smem_to_u32(const void* p) {
    uint32_t a;
    asm("{ .reg .u64 t; cvta.to.shared.u64 t, %1; cvt.u32.u64 %0, t; }" : "=r"(a) : "l"(p));
    return a;
}

#define CP_ASYNC16(dst, src) \
    asm volatile("cp.async.cg.shared.global [%0], [%1], 16;" :: "r"(dst), "l"(src) : "memory")
#define CP_COMMIT() asm volatile("cp.async.commit_group;" ::: "memory")
#define CP_WAIT0()  asm volatile("cp.async.wait_group 0;" ::: "memory")
#define CP_WAIT1()  asm volatile("cp.async.wait_group 1;" ::: "memory")

#define LDSM_X4(r0, r1, r2, r3, addr) \
    asm volatile("ldmatrix.sync.aligned.m8n8.x4.shared.b16 {%0,%1,%2,%3}, [%4];" \
        : "=r"(r0), "=r"(r1), "=r"(r2), "=r"(r3) : "r"(addr))

__device__ __forceinline__ void mma16816(float* c, const uint32_t* a, uint32_t b0, uint32_t b1) {
    asm volatile(
        "mma.sync.aligned.m16n8k16.row.col.f32.f16.f16.f32 "
        "{%0,%1,%2,%3}, {%4,%5,%6,%7}, {%8,%9}, {%0,%1,%2,%3};"
        : "+f"(c[0]), "+f"(c[1]), "+f"(c[2]), "+f"(c[3])
        : "r"(a[0]), "r"(a[1]), "r"(a[2]), "r"(a[3]), "r"(b0), "r"(b1));
}

// ---------------- device-global scratch ----------------
__device__ __align__(256) __half g_xT[(size_t)DIN * NN];       // x^T [512,8192]
__device__ __align__(256) __half g_Acat[(size_t)NN * 1024];    // [x | agg] fp16
__device__ __align__(256) __half g_BtUV[(size_t)DOUT * 1024];  // [U;V]^T: [n][k]
__device__ __align__(256) float g_S1[(size_t)NN * DOUT];
__device__ __align__(256) float g_deg[NN];
__device__ __align__(256) float g_beff[DOUT];

// ---------------- prep: x -> Acat left half + transposed fp16 ----------------
__global__ void prep_x_kernel(const float* __restrict__ x) {
    __shared__ __half sh[32][33];
    int tx = threadIdx.x, ty = threadIdx.y;
    int d0 = blockIdx.x * 32, m0 = blockIdx.y * 32;
#pragma unroll
    for (int r = 0; r < 4; r++) {
        int mm = ty + r * 8, m = m0 + mm;
        __half h = __float2half_rn(x[(size_t)m * DIN + d0 + tx]);
        g_Acat[(size_t)m * 1024 + d0 + tx] = h;
        sh[mm][tx] = h;
    }
    __syncthreads();
#pragma unroll
    for (int r = 0; r < 4; r++) {
        int dd = ty + r * 8, d = d0 + dd, m = m0 + tx;
        g_xT[(size_t)d * NN + m] = sh[tx][dd];
    }
}

// ---------------- wprod: U = Ws@Wc_top, V = Wn@Wc_bot -> g_BtUV fp16 ----------------
__global__ void wprod_kernel(const float* __restrict__ Ws, const float* __restrict__ Wn,
                             const float* __restrict__ Wc) {
    __shared__ float sA[32][33], sB[32][33];
    int tx = threadIdx.x, ty = threadIdx.y;
    bool second = blockIdx.y >= 16;
    const float* A = second ? Wn : Ws;           // A[k][j], 512x512
    int k0 = (blockIdx.y & 15) * 32;
    int n0 = blockIdx.x * 32;
    int jb = second ? 512 : 0;                   // Wc row offset
    float acc[4] = {0.f, 0.f, 0.f, 0.f};
    for (int j0 = 0; j0 < 512; j0 += 32) {
#pragma unroll
        for (int r = 0; r < 4; r++) {
            sA[ty + r * 8][tx] = A[(size_t)(k0 + ty + r * 8) * 512 + j0 + tx];
            sB[ty + r * 8][tx] = Wc[(size_t)(jb + j0 + ty + r * 8) * 512 + n0 + tx];
        }
        __syncthreads();
#pragma unroll
        for (int j = 0; j < 32; j++) {
            float b = sB[j][tx];
            acc[0] += sA[ty][j] * b;
            acc[1] += sA[ty + 8][j] * b;
            acc[2] += sA[ty + 16][j] * b;
            acc[3] += sA[ty + 24][j] * b;
        }
        __syncthreads();
    }
#pragma unroll
    for (int r = 0; r < 4; r++) {
        int k = (second ? 512 : 0) + k0 + ty + r * 8;
        g_BtUV[(size_t)(n0 + tx) * 1024 + k] = __float2half_rn(acc[r]);
    }
}

// ---------------- b_eff = bs@Wc_top + bn@Wc_bot + bc (parallel) ----------------
__global__ void beff_kernel(const float* __restrict__ bs, const float* __restrict__ bn,
                            const float* __restrict__ bc, const float* __restrict__ Wc) {
    __shared__ float red[256];
    int n = blockIdx.x;         // 512 blocks
    int t = threadIdx.x;        // 256 threads
    float acc = 0.0f;
    for (int j = t; j < 512; j += 256)
        acc += bs[j] * Wc[(size_t)j * 512 + n] + bn[j] * Wc[(size_t)(512 + j) * 512 + n];
    red[t] = acc;
    __syncthreads();
    for (int s = 128; s > 0; s >>= 1) {
        if (t < s) red[t] += red[t + s];
        __syncthreads();
    }
    if (t == 0) g_beff[n] = red[0] + bc[n];
}

// ---------------- agg = S1/max(deg,1) -> Acat right half ----------------
__global__ void agg_split_kernel() {
    int t = blockIdx.x * 256 + threadIdx.x;  // NN*128 threads
    int m = t >> 7, d4 = (t & 127) * 4;
    float inv = 1.0f / fmaxf(g_deg[m], 1.0f);
    float4 s = *reinterpret_cast<const float4*>(g_S1 + (size_t)m * DOUT + d4);
    __half2* p = reinterpret_cast<__half2*>(g_Acat + (size_t)m * 1024 + 512 + d4);
    p[0] = __halves2half2(__float2half_rn(s.x * inv), __float2half_rn(s.y * inv));
    p[1] = __halves2half2(__float2half_rn(s.z * inv), __float2half_rn(s.w * inv));
}

// ============================================================================
// GEMMs: CTA tile 128x256, 512 threads (16 warps, warp tile 32x64).
// Padded-linear smem row stride 144 B; ldmatrix mappings verified in R10-R13.
// ============================================================================
static constexpr int RSTR = 144;
static constexpr int AT_SZ = 128 * RSTR;              // 18432
static constexpr int BT_SZ = 256 * RSTR;              // 36864
static constexpr int G_STAGE = AT_SZ + BT_SZ;         // 55296
static constexpr int G1_SMEM = 1024 + 2 * G_STAGE;    // 111616
static constexpr int GF_SMEM = 2 * G_STAGE;           // 110592

__global__ void __launch_bounds__(512, 1)
gemm1_kernel(const int* __restrict__ adj) {
    extern __shared__ char smem[];
    uint32_t sb = smem_to_u32(smem);
    int tid = threadIdx.x, wid = tid >> 5, lane = tid & 31;
    int m0 = blockIdx.y * 128, n0 = blockIdx.x * 256;
    bool dodeg = (blockIdx.x == 0);
    int* degsm = reinterpret_cast<int*>(smem);
    if (tid < 128) degsm[tid] = 0;

    const int wm = (wid & 3) * 32;     // warp m-offset (4 x 32)
    const int wn = (wid >> 2) * 64;    // warp n-offset (4 x 64)

    const int a_row = ((lane >> 3) & 1) * 8 + (lane & 7);
    const int a_koff = (lane >> 4) * 16;
    const int b_row = ((lane >> 4) & 1) * 8 + (lane & 7);
    const int b_koff = ((lane >> 3) & 1) * 16;

    float c[2][8][4];
#pragma unroll
    for (int i = 0; i < 2; i++)
#pragma unroll
        for (int j = 0; j < 8; j++)
#pragma unroll
            for (int q = 0; q < 4; q++) c[i][j][q] = 0.0f;

    int4 av[2][2];
    int dacc[2] = {0, 0};

    auto ldA = [&](int k0) {
#pragma unroll
        for (int i = 0; i < 2; i++) {
            int idx = i * 512 + tid;
            int r = idx >> 3, cc = idx & 7;
            const int4* p = reinterpret_cast<const int4*>(
                adj + (size_t)(m0 + r) * NN + k0 + cc * 8);
            av[i][0] = p[0]; av[i][1] = p[1];
        }
    };
    auto stA = [&](uint32_t abase) {
#pragma unroll
        for (int i = 0; i < 2; i++) {
            int idx = i * 512 + tid;
            int r = idx >> 3, cc = idx & 7;
            uint32_t p0 = ((av[i][0].x > 0) ? 0x3C00u : 0u) | ((av[i][0].y > 0) ? 0x3C000000u : 0u);
            uint32_t p1 = ((av[i][0].z > 0) ? 0x3C00u : 0u) | ((av[i][0].w > 0) ? 0x3C000000u : 0u);
            uint32_t p2 = ((av[i][1].x > 0) ? 0x3C00u : 0u) | ((av[i][1].y > 0) ? 0x3C000000u : 0u);
            uint32_t p3 = ((av[i][1].z > 0) ? 0x3C00u : 0u) | ((av[i][1].w > 0) ? 0x3C000000u : 0u);
            if (dodeg)
                dacc[i] += (av[i][0].x > 0) + (av[i][0].y > 0) + (av[i][0].z > 0) + (av[i][0].w > 0)
                         + (av[i][1].x > 0) + (av[i][1].y > 0) + (av[i][1].z > 0) + (av[i][1].w > 0);
            asm volatile("st.shared.v4.b32 [%0], {%1,%2,%3,%4};"
                         :: "r"(abase + (uint32_t)(r * RSTR + cc * 16)),
                            "r"(p0), "r"(p1), "r"(p2), "r"(p3) : "memory");
        }
    };
    auto ldB = [&](uint32_t bbase, int k0) {
#pragma unroll
        for (int i = 0; i < 4; i++) {
            int idx = i * 512 + tid;
            int r = idx >> 3, cc = idx & 7;
            CP_ASYNC16(bbase + (uint32_t)(r * RSTR + cc * 16),
                       reinterpret_cast<const char*>(g_xT) + ((size_t)(n0 + r) * NN + k0 + cc * 8) * 2);
        }
    };
    auto compute = [&](uint32_t base) {
        uint32_t aB = base + AT_SZ;
#pragma unroll
        for (int s4 = 0; s4 < 4; s4++) {
            uint32_t a[2][4];
#pragma unroll
            for (int ms = 0; ms < 2; ms++) {
                uint32_t ad = base + (uint32_t)((wm + ms * 16 + a_row) * RSTR + s4 * 32 + a_koff);
                LDSM_X4(a[ms][0], a[ms][1], a[ms][2], a[ms][3], ad);
            }
#pragma unroll
            for (int pp = 0; pp < 4; pp++) {
                uint32_t bd = aB + (uint32_t)((wn + pp * 16 + b_row) * RSTR + s4 * 32 + b_koff);
                uint32_t b0, b1, b2, b3;
                LDSM_X4(b0, b1, b2, b3, bd);
                mma16816(c[0][2 * pp],     a[0], b0, b1);
                mma16816(c[1][2 * pp],     a[1], b0, b1);
                mma16816(c[0][2 * pp + 1], a[0], b2, b3);
                mma16816(c[1][2 * pp + 1], a[1], b2, b3);
            }
        }
    };

    // prologue
    uint32_t st0 = sb + 1024;
    ldA(0);
    ldB(st0 + AT_SZ, 0);
    CP_COMMIT();
    stA(st0);

    const int NIT = NN / 64;  // 128
    for (int it = 0; it < NIT; it++) {
        int s = it & 1;
        uint32_t cur = sb + 1024 + s * G_STAGE;
        uint32_t nxt = sb + 1024 + (1 - s) * G_STAGE;
        bool more = (it + 1 < NIT);
        if (more) {
            int k0 = (it + 1) * 64;
            ldA(k0);
            ldB(nxt + AT_SZ, k0);
            CP_COMMIT();
            CP_WAIT1();
        } else {
            CP_WAIT0();
        }
        __syncthreads();
        compute(cur);
        if (more) stA(nxt);
        __syncthreads();
    }

    // epilogue: raw sums to g_S1
#pragma unroll
    for (int ms = 0; ms < 2; ms++) {
        int row = m0 + wm + ms * 16 + (lane >> 2);
#pragma unroll
        for (int ns = 0; ns < 8; ns++) {
            int col = n0 + wn + ns * 8 + 2 * (lane & 3);
            *reinterpret_cast<float2*>(g_S1 + (size_t)row * DOUT + col) =
                make_float2(c[ms][ns][0], c[ms][ns][1]);
            *reinterpret_cast<float2*>(g_S1 + (size_t)(row + 8) * DOUT + col) =
                make_float2(c[ms][ns][2], c[ms][ns][3]);
        }
    }
    if (dodeg) {
#pragma unroll
        for (int i = 0; i < 2; i++) atomicAdd(&degsm[(i * 512 + tid) >> 3], dacc[i]);
        __syncthreads();
        if (tid < 128) g_deg[m0 + tid] = (float)degsm[tid];
    }
}

// ============================================================================
// Final GEMM: out = relu([x|agg] @ [U;V]^T + b_eff), M=8192, N=512, K=1024
// ============================================================================
__global__ void __launch_bounds__(512, 1)
gemm_final_kernel(float* __restrict__ outf) {
    extern __shared__ char smem[];
    uint32_t sb = smem_to_u32(smem);
    int tid = threadIdx.x, wid = tid >> 5, lane = tid & 31;
    int m0 = blockIdx.y * 128, n0 = blockIdx.x * 256;

    const int wm = (wid & 3) * 32, wn = (wid >> 2) * 64;
    const int a_row = ((lane >> 3) & 1) * 8 + (lane & 7);
    const int a_koff = (lane >> 4) * 16;
    const int b_row = ((lane >> 4) & 1) * 8 + (lane & 7);
    const int b_koff = ((lane >> 3) & 1) * 16;

    float c[2][8][4];
#pragma unroll
    for (int i = 0; i < 2; i++)
#pragma unroll
        for (int j = 0; j < 8; j++)
#pragma unroll
            for (int q = 0; q < 4; q++) c[i][j][q] = 0.0f;

    auto ldA = [&](uint32_t abase, int k0) {
#pragma unroll
        for (int i = 0; i < 2; i++) {
            int idx = i * 512 + tid;
            int r = idx >> 3, cc = idx & 7;
            CP_ASYNC16(abase + (uint32_t)(r * RSTR + cc * 16),
                       reinterpret_cast<const char*>(g_Acat) + ((size_t)(m0 + r) * 1024 + k0 + cc * 8) * 2);
        }
    };
    auto ldB = [&](uint32_t bbase, int k0) {
#pragma unroll
        for (int i = 0; i < 4; i++) {
            int idx = i * 512 + tid;
            int r = idx >> 3, cc = idx & 7;
            CP_ASYNC16(bbase + (uint32_t)(r * RSTR + cc * 16),
                       reinterpret_cast<const char*>(g_BtUV) + ((size_t)(n0 + r) * 1024 + k0 + cc * 8) * 2);
        }
    };
    auto compute = [&](uint32_t base) {
        uint32_t aB = base + AT_SZ;
#pragma unroll
        for (int s4 = 0; s4 < 4; s4++) {
            uint32_t a[2][4];
#pragma unroll
            for (int ms = 0; ms < 2; ms++) {
                uint32_t ad = base + (uint32_t)((wm + ms * 16 + a_row) * RSTR + s4 * 32 + a_koff);
                LDSM_X4(a[ms][0], a[ms][1], a[ms][2], a[ms][3], ad);
            }
#pragma unroll
            for (int pp = 0; pp < 4; pp++) {
                uint32_t bd = aB + (uint32_t)((wn + pp * 16 + b_row) * RSTR + s4 * 32 + b_koff);
                uint32_t b0, b1, b2, b3;
                LDSM_X4(b0, b1, b2, b3, bd);
                mma16816(c[0][2 * pp],     a[0], b0, b1);
                mma16816(c[1][2 * pp],     a[1], b0, b1);
                mma16816(c[0][2 * pp + 1], a[0], b2, b3);
                mma16816(c[1][2 * pp + 1], a[1], b2, b3);
            }
        }
    };

    ldA(sb, 0); ldB(sb + AT_SZ, 0); CP_COMMIT();

    const int NIT = 1024 / 64;  // 16
    for (int it = 0; it < NIT; it++) {
        int s = it & 1;
        uint32_t cur = sb + s * G_STAGE;
        uint32_t nxt = sb + (1 - s) * G_STAGE;
        bool more = (it + 1 < NIT);
        if (more) {
            int k0 = (it + 1) * 64;
            ldA(nxt, k0); ldB(nxt + AT_SZ, k0); CP_COMMIT();
            CP_WAIT1();
        } else {
            CP_WAIT0();
        }
        __syncthreads();
        compute(cur);
        __syncthreads();
    }

    // epilogue: bias + relu -> out
#pragma unroll
    for (int ms = 0; ms < 2; ms++) {
        int row = m0 + wm + ms * 16 + (lane >> 2);
#pragma unroll
        for (int ns = 0; ns < 8; ns++) {
            int col = n0 + wn + ns * 8 + 2 * (lane & 3);
            float b0 = g_beff[col], b1 = g_beff[col + 1];
            *reinterpret_cast<float2*>(outf + (size_t)row * DOUT + col) =
                make_float2(fmaxf(c[ms][ns][0] + b0, 0.0f), fmaxf(c[ms][ns][1] + b1, 0.0f));
            *reinterpret_cast<float2*>(outf + (size_t)(row + 8) * DOUT + col) =
                make_float2(fmaxf(c[ms][ns][2] + b0, 0.0f), fmaxf(c[ms][ns][3] + b1, 0.0f));
        }
    }
}

// ---------------- launcher (inputs resolved by element count) ----------------
extern "C" void kernel_launch(void* const* d_in, const int* in_sizes, int n_in,
                              void* d_out, int out_size) {
    const float* x = nullptr; const int* adj = nullptr;
    const float *Ws = nullptr, *bs = nullptr, *Wn = nullptr, *bn = nullptr;
    const float *Wc = nullptr, *bc = nullptr;
    for (int i = 0; i < n_in; i++) {
        long long s = in_sizes[i];
        const void* p = d_in[i];
        if (s == (long long)NN * NN)            adj = (const int*)p;
        else if (s == (long long)NN * DIN)      x = (const float*)p;
        else if (s == (long long)2 * DOUT * DOUT) Wc = (const float*)p;
        else if (s == (long long)DIN * DOUT) { if (!Ws) Ws = (const float*)p; else Wn = (const float*)p; }
        else if (s == DOUT) { if (!bs) bs = (const float*)p; else if (!bn) bn = (const float*)p; else bc = (const float*)p; }
    }
    float* out = (float*)d_out;

    cudaFuncSetAttribute(gemm1_kernel, cudaFuncAttributeMaxDynamicSharedMemorySize, G1_SMEM);
    cudaFuncSetAttribute(gemm_final_kernel, cudaFuncAttributeMaxDynamicSharedMemorySize, GF_SMEM);

    prep_x_kernel<<<dim3(16, 256), dim3(32, 8)>>>(x);
    wprod_kernel<<<dim3(16, 32), dim3(32, 8)>>>(Ws, Wn, Wc);
    beff_kernel<<<512, 256>>>(bs, bn, bc, Wc);
    gemm1_kernel<<<dim3(2, 64), 512, G1_SMEM>>>(adj);
    agg_split_kernel<<<4096, 256>>>();
    gemm_final_kernel<<<dim3(2, 64), 512, GF_SMEM>>>(out);
}

// round 16
// speedup vs baseline: 1.4686x; 1.4686x over previous
#include <cuda_runtime.h>
#include <cuda_fp16.h>
#include <cstdint>

#define NN    8192
#define DIN   512
#define DOUT  512

// ---------------- helpers ----------------
__device__ __forceinline__ uint32_t smem_to_u32(const void* p) {
    uint32_t a;
    asm("{ .reg .u64 t; cvta.to.shared.u64 t, %1; cvt.u32.u64 %0, t; }" : "=r"(a) : "l"(p));
    return a;
}

#define CP_ASYNC16(dst, src) \
    asm volatile("cp.async.cg.shared.global [%0], [%1], 16;" :: "r"(dst), "l"(src) : "memory")
#define CP_COMMIT() asm volatile("cp.async.commit_group;" ::: "memory")
#define CP_WAIT0()  asm volatile("cp.async.wait_group 0;" ::: "memory")
#define CP_WAIT1()  asm volatile("cp.async.wait_group 1;" ::: "memory")

#define LDSM_X4(r0, r1, r2, r3, addr) \
    asm volatile("ldmatrix.sync.aligned.m8n8.x4.shared.b16 {%0,%1,%2,%3}, [%4];" \
        : "=r"(r0), "=r"(r1), "=r"(r2), "=r"(r3) : "r"(addr))

__device__ __forceinline__ void mma16816(float* c, const uint32_t* a, uint32_t b0, uint32_t b1) {
    asm volatile(
        "mma.sync.aligned.m16n8k16.row.col.f32.f16.f16.f32 "
        "{%0,%1,%2,%3}, {%4,%5,%6,%7}, {%8,%9}, {%0,%1,%2,%3};"
        : "+f"(c[0]), "+f"(c[1]), "+f"(c[2]), "+f"(c[3])
        : "r"(a[0]), "r"(a[1]), "r"(a[2]), "r"(a[3]), "r"(b0), "r"(b1));
}

// ---------------- device-global scratch ----------------
__device__ __align__(256) __half g_xT[(size_t)DIN * NN];       // x^T [512,8192]
__device__ __align__(256) __half g_Acat[(size_t)NN * 1024];    // [x | agg] fp16
__device__ __align__(256) __half g_BtUV[(size_t)DOUT * 1024];  // [U;V]^T: [n][k]
__device__ __align__(256) float g_S1[(size_t)NN * DOUT];
__device__ __align__(256) float g_deg[NN];
__device__ __align__(256) float g_beff[DOUT];

// ---------------- prep: x -> Acat left half + transposed fp16 ----------------
__global__ void prep_x_kernel(const float* __restrict__ x) {
    __shared__ __half sh[32][33];
    int tx = threadIdx.x, ty = threadIdx.y;
    int d0 = blockIdx.x * 32, m0 = blockIdx.y * 32;
#pragma unroll
    for (int r = 0; r < 4; r++) {
        int mm = ty + r * 8, m = m0 + mm;
        __half h = __float2half_rn(x[(size_t)m * DIN + d0 + tx]);
        g_Acat[(size_t)m * 1024 + d0 + tx] = h;
        sh[mm][tx] = h;
    }
    __syncthreads();
#pragma unroll
    for (int r = 0; r < 4; r++) {
        int dd = ty + r * 8, d = d0 + dd, m = m0 + tx;
        g_xT[(size_t)d * NN + m] = sh[tx][dd];
    }
}

// ---------------- wprod: U = Ws@Wc_top, V = Wn@Wc_bot -> g_BtUV fp16 ----------------
__global__ void wprod_kernel(const float* __restrict__ Ws, const float* __restrict__ Wn,
                             const float* __restrict__ Wc) {
    __shared__ float sA[32][33], sB[32][33];
    int tx = threadIdx.x, ty = threadIdx.y;
    bool second = blockIdx.y >= 16;
    const float* A = second ? Wn : Ws;           // A[k][j], 512x512
    int k0 = (blockIdx.y & 15) * 32;
    int n0 = blockIdx.x * 32;
    int jb = second ? 512 : 0;                   // Wc row offset
    float acc[4] = {0.f, 0.f, 0.f, 0.f};
    for (int j0 = 0; j0 < 512; j0 += 32) {
#pragma unroll
        for (int r = 0; r < 4; r++) {
            sA[ty + r * 8][tx] = A[(size_t)(k0 + ty + r * 8) * 512 + j0 + tx];
            sB[ty + r * 8][tx] = Wc[(size_t)(jb + j0 + ty + r * 8) * 512 + n0 + tx];
        }
        __syncthreads();
#pragma unroll
        for (int j = 0; j < 32; j++) {
            float b = sB[j][tx];
            acc[0] += sA[ty][j] * b;
            acc[1] += sA[ty + 8][j] * b;
            acc[2] += sA[ty + 16][j] * b;
            acc[3] += sA[ty + 24][j] * b;
        }
        __syncthreads();
    }
#pragma unroll
    for (int r = 0; r < 4; r++) {
        int k = (second ? 512 : 0) + k0 + ty + r * 8;
        g_BtUV[(size_t)(n0 + tx) * 1024 + k] = __float2half_rn(acc[r]);
    }
}

// ---------------- b_eff = bs@Wc_top + bn@Wc_bot + bc (parallel, fixed) ----------------
__global__ void beff_kernel(const float* __restrict__ bs, const float* __restrict__ bn,
                            const float* __restrict__ bc, const float* __restrict__ Wc) {
    __shared__ float red[256];
    int n = blockIdx.x;         // 512 blocks
    int t = threadIdx.x;        // 256 threads
    float acc = 0.0f;
    for (int j = t; j < 512; j += 256)
        acc += bs[j] * Wc[(size_t)j * 512 + n] + bn[j] * Wc[(size_t)(512 + j) * 512 + n];
    red[t] = acc;
    __syncthreads();
    for (int s = 128; s > 0; s >>= 1) {
        if (t < s) red[t] += red[t + s];
        __syncthreads();
    }
    if (t == 0) g_beff[n] = red[0] + bc[n];
}

// ---------------- agg = S1/max(deg,1) -> Acat right half ----------------
__global__ void agg_split_kernel() {
    int t = blockIdx.x * 256 + threadIdx.x;  // NN*128 threads
    int m = t >> 7, d4 = (t & 127) * 4;
    float inv = 1.0f / fmaxf(g_deg[m], 1.0f);
    float4 s = *reinterpret_cast<const float4*>(g_S1 + (size_t)m * DOUT + d4);
    __half2* p = reinterpret_cast<__half2*>(g_Acat + (size_t)m * 1024 + 512 + d4);
    p[0] = __halves2half2(__float2half_rn(s.x * inv), __float2half_rn(s.y * inv));
    p[1] = __halves2half2(__float2half_rn(s.z * inv), __float2half_rn(s.w * inv));
}

// ============================================================================
// GEMMs: CTA tile 128x256, 256 threads (8 warps, warp tile 32x128) — the
// measured-good R13 shape. Padded-linear smem row stride 144 B; ldmatrix.
// ============================================================================
static constexpr int RSTR = 144;
static constexpr int AT_SZ = 128 * RSTR;              // 18432
static constexpr int BT_SZ = 256 * RSTR;              // 36864
static constexpr int G_STAGE = AT_SZ + BT_SZ;         // 55296
static constexpr int G1_SMEM = 1024 + 2 * G_STAGE;    // 111616
static constexpr int GF_SMEM = 2 * G_STAGE;           // 110592

__global__ void __launch_bounds__(256, 1)
gemm1_kernel(const int* __restrict__ adj) {
    extern __shared__ char smem[];
    uint32_t sb = smem_to_u32(smem);
    int tid = threadIdx.x, wid = tid >> 5, lane = tid & 31;
    int m0 = blockIdx.y * 128, n0 = blockIdx.x * 256;
    bool dodeg = (blockIdx.x == 0);
    int* degsm = reinterpret_cast<int*>(smem);
    if (tid < 128) degsm[tid] = 0;

    const int wm = (wid & 3) * 32;     // warp m-offset
    const int wn = (wid >> 2) * 128;   // warp n-offset

    const int a_row = ((lane >> 3) & 1) * 8 + (lane & 7);
    const int a_koff = (lane >> 4) * 16;
    const int b_row = ((lane >> 4) & 1) * 8 + (lane & 7);
    const int b_koff = ((lane >> 3) & 1) * 16;

    float c[2][16][4];
#pragma unroll
    for (int i = 0; i < 2; i++)
#pragma unroll
        for (int j = 0; j < 16; j++)
#pragma unroll
            for (int q = 0; q < 4; q++) c[i][j][q] = 0.0f;

    int4 av[4][2];
    int dacc[4] = {0, 0, 0, 0};

    auto ldA = [&](int k0) {
#pragma unroll
        for (int i = 0; i < 4; i++) {
            int idx = i * 256 + tid;
            int r = idx >> 3, cc = idx & 7;
            const int4* p = reinterpret_cast<const int4*>(
                adj + (size_t)(m0 + r) * NN + k0 + cc * 8);
            av[i][0] = p[0]; av[i][1] = p[1];
        }
    };
    auto stA = [&](uint32_t abase) {
#pragma unroll
        for (int i = 0; i < 4; i++) {
            int idx = i * 256 + tid;
            int r = idx >> 3, cc = idx & 7;
            uint32_t p0 = ((av[i][0].x > 0) ? 0x3C00u : 0u) | ((av[i][0].y > 0) ? 0x3C000000u : 0u);
            uint32_t p1 = ((av[i][0].z > 0) ? 0x3C00u : 0u) | ((av[i][0].w > 0) ? 0x3C000000u : 0u);
            uint32_t p2 = ((av[i][1].x > 0) ? 0x3C00u : 0u) | ((av[i][1].y > 0) ? 0x3C000000u : 0u);
            uint32_t p3 = ((av[i][1].z > 0) ? 0x3C00u : 0u) | ((av[i][1].w > 0) ? 0x3C000000u : 0u);
            if (dodeg)
                dacc[i] += (av[i][0].x > 0) + (av[i][0].y > 0) + (av[i][0].z > 0) + (av[i][0].w > 0)
                         + (av[i][1].x > 0) + (av[i][1].y > 0) + (av[i][1].z > 0) + (av[i][1].w > 0);
            asm volatile("st.shared.v4.b32 [%0], {%1,%2,%3,%4};"
                         :: "r"(abase + (uint32_t)(r * RSTR + cc * 16)),
                            "r"(p0), "r"(p1), "r"(p2), "r"(p3) : "memory");
        }
    };
    auto ldB = [&](uint32_t bbase, int k0) {
#pragma unroll
        for (int i = 0; i < 8; i++) {
            int idx = i * 256 + tid;
            int r = idx >> 3, cc = idx & 7;
            CP_ASYNC16(bbase + (uint32_t)(r * RSTR + cc * 16),
                       reinterpret_cast<const char*>(g_xT) + ((size_t)(n0 + r) * NN + k0 + cc * 8) * 2);
        }
    };
    auto compute = [&](uint32_t base) {
        uint32_t aB = base + AT_SZ;
#pragma unroll
        for (int s4 = 0; s4 < 4; s4++) {
            uint32_t a[2][4];
#pragma unroll
            for (int ms = 0; ms < 2; ms++) {
                uint32_t ad = base + (uint32_t)((wm + ms * 16 + a_row) * RSTR + s4 * 32 + a_koff);
                LDSM_X4(a[ms][0], a[ms][1], a[ms][2], a[ms][3], ad);
            }
#pragma unroll
            for (int pp = 0; pp < 8; pp++) {
                uint32_t bd = aB + (uint32_t)((wn + pp * 16 + b_row) * RSTR + s4 * 32 + b_koff);
                uint32_t b0, b1, b2, b3;
                LDSM_X4(b0, b1, b2, b3, bd);
                mma16816(c[0][2 * pp],     a[0], b0, b1);
                mma16816(c[1][2 * pp],     a[1], b0, b1);
                mma16816(c[0][2 * pp + 1], a[0], b2, b3);
                mma16816(c[1][2 * pp + 1], a[1], b2, b3);
            }
        }
    };

    // prologue
    uint32_t st0 = sb + 1024;
    ldA(0);
    ldB(st0 + AT_SZ, 0);
    CP_COMMIT();
    stA(st0);

    const int NIT = NN / 64;  // 128
    for (int it = 0; it < NIT; it++) {
        int s = it & 1;
        uint32_t cur = sb + 1024 + s * G_STAGE;
        uint32_t nxt = sb + 1024 + (1 - s) * G_STAGE;
        bool more = (it + 1 < NIT);
        if (more) {
            int k0 = (it + 1) * 64;
            ldA(k0);
            ldB(nxt + AT_SZ, k0);
            CP_COMMIT();
            CP_WAIT1();
        } else {
            CP_WAIT0();
        }
        __syncthreads();
        compute(cur);
        if (more) stA(nxt);
        __syncthreads();
    }

    // epilogue: raw sums to g_S1
#pragma unroll
    for (int ms = 0; ms < 2; ms++) {
        int row = m0 + wm + ms * 16 + (lane >> 2);
#pragma unroll
        for (int ns = 0; ns < 16; ns++) {
            int col = n0 + wn + ns * 8 + 2 * (lane & 3);
            *reinterpret_cast<float2*>(g_S1 + (size_t)row * DOUT + col) =
                make_float2(c[ms][ns][0], c[ms][ns][1]);
            *reinterpret_cast<float2*>(g_S1 + (size_t)(row + 8) * DOUT + col) =
                make_float2(c[ms][ns][2], c[ms][ns][3]);
        }
    }
    if (dodeg) {
#pragma unroll
        for (int i = 0; i < 4; i++) atomicAdd(&degsm[(i * 256 + tid) >> 3], dacc[i]);
        __syncthreads();
        if (tid < 128) g_deg[m0 + tid] = (float)degsm[tid];
    }
}

// ============================================================================
// Final GEMM: out = relu([x|agg] @ [U;V]^T + b_eff), M=8192, N=512, K=1024
// ============================================================================
__global__ void __launch_bounds__(256, 1)
gemm_final_kernel(float* __restrict__ outf) {
    extern __shared__ char smem[];
    uint32_t sb = smem_to_u32(smem);
    int tid = threadIdx.x, wid = tid >> 5, lane = tid & 31;
    int m0 = blockIdx.y * 128, n0 = blockIdx.x * 256;

    const int wm = (wid & 3) * 32, wn = (wid >> 2) * 128;
    const int a_row = ((lane >> 3) & 1) * 8 + (lane & 7);
    const int a_koff = (lane >> 4) * 16;
    const int b_row = ((lane >> 4) & 1) * 8 + (lane & 7);
    const int b_koff = ((lane >> 3) & 1) * 16;

    float c[2][16][4];
#pragma unroll
    for (int i = 0; i < 2; i++)
#pragma unroll
        for (int j = 0; j < 16; j++)
#pragma unroll
            for (int q = 0; q < 4; q++) c[i][j][q] = 0.0f;

    auto ldA = [&](uint32_t abase, int k0) {
#pragma unroll
        for (int i = 0; i < 4; i++) {
            int idx = i * 256 + tid;
            int r = idx >> 3, cc = idx & 7;
            CP_ASYNC16(abase + (uint32_t)(r * RSTR + cc * 16),
                       reinterpret_cast<const char*>(g_Acat) + ((size_t)(m0 + r) * 1024 + k0 + cc * 8) * 2);
        }
    };
    auto ldB = [&](uint32_t bbase, int k0) {
#pragma unroll
        for (int i = 0; i < 8; i++) {
            int idx = i * 256 + tid;
            int r = idx >> 3, cc = idx & 7;
            CP_ASYNC16(bbase + (uint32_t)(r * RSTR + cc * 16),
                       reinterpret_cast<const char*>(g_BtUV) + ((size_t)(n0 + r) * 1024 + k0 + cc * 8) * 2);
        }
    };
    auto compute = [&](uint32_t base) {
        uint32_t aB = base + AT_SZ;
#pragma unroll
        for (int s4 = 0; s4 < 4; s4++) {
            uint32_t a[2][4];
#pragma unroll
            for (int ms = 0; ms < 2; ms++) {
                uint32_t ad = base + (uint32_t)((wm + ms * 16 + a_row) * RSTR + s4 * 32 + a_koff);
                LDSM_X4(a[ms][0], a[ms][1], a[ms][2], a[ms][3], ad);
            }
#pragma unroll
            for (int pp = 0; pp < 8; pp++) {
                uint32_t bd = aB + (uint32_t)((wn + pp * 16 + b_row) * RSTR + s4 * 32 + b_koff);
                uint32_t b0, b1, b2, b3;
                LDSM_X4(b0, b1, b2, b3, bd);
                mma16816(c[0][2 * pp],     a[0], b0, b1);
                mma16816(c[1][2 * pp],     a[1], b0, b1);
                mma16816(c[0][2 * pp + 1], a[0], b2, b3);
                mma16816(c[1][2 * pp + 1], a[1], b2, b3);
            }
        }
    };

    ldA(sb, 0); ldB(sb + AT_SZ, 0); CP_COMMIT();

    const int NIT = 1024 / 64;  // 16
    for (int it = 0; it < NIT; it++) {
        int s = it & 1;
        uint32_t cur = sb + s * G_STAGE;
        uint32_t nxt = sb + (1 - s) * G_STAGE;
        bool more = (it + 1 < NIT);
        if (more) {
            int k0 = (it + 1) * 64;
            ldA(nxt, k0); ldB(nxt + AT_SZ, k0); CP_COMMIT();
            CP_WAIT1();
        } else {
            CP_WAIT0();
        }
        __syncthreads();
        compute(cur);
        __syncthreads();
    }

    // epilogue: bias + relu -> out
#pragma unroll
    for (int ms = 0; ms < 2; ms++) {
        int row = m0 + wm + ms * 16 + (lane >> 2);
#pragma unroll
        for (int ns = 0; ns < 16; ns++) {
            int col = n0 + wn + ns * 8 + 2 * (lane & 3);
            float b0 = g_beff[col], b1 = g_beff[col + 1];
            *reinterpret_cast<float2*>(outf + (size_t)row * DOUT + col) =
                make_float2(fmaxf(c[ms][ns][0] + b0, 0.0f), fmaxf(c[ms][ns][1] + b1, 0.0f));
            *reinterpret_cast<float2*>(outf + (size_t)(row + 8) * DOUT + col) =
                make_float2(fmaxf(c[ms][ns][2] + b0, 0.0f), fmaxf(c[ms][ns][3] + b1, 0.0f));
        }
    }
}

// ---------------- launcher (inputs resolved by element count) ----------------
extern "C" void kernel_launch(void* const* d_in, const int* in_sizes, int n_in,
                              void* d_out, int out_size) {
    const float* x = nullptr; const int* adj = nullptr;
    const float *Ws = nullptr, *bs = nullptr, *Wn = nullptr, *bn = nullptr;
    const float *Wc = nullptr, *bc = nullptr;
    for (int i = 0; i < n_in; i++) {
        long long s = in_sizes[i];
        const void* p = d_in[i];
        if (s == (long long)NN * NN)            adj = (const int*)p;
        else if (s == (long long)NN * DIN)      x = (const float*)p;
        else if (s == (long long)2 * DOUT * DOUT) Wc = (const float*)p;
        else if (s == (long long)DIN * DOUT) { if (!Ws) Ws = (const float*)p; else Wn = (const float*)p; }
        else if (s == DOUT) { if (!bs) bs = (const float*)p; else if (!bn) bn = (const float*)p; else bc = (const float*)p; }
    }
    float* out = (float*)d_out;

    cudaFuncSetAttribute(gemm1_kernel, cudaFuncAttributeMaxDynamicSharedMemorySize, G1_SMEM);
    cudaFuncSetAttribute(gemm_final_kernel, cudaFuncAttributeMaxDynamicSharedMemorySize, GF_SMEM);

    prep_x_kernel<<<dim3(16, 256), dim3(32, 8)>>>(x);
    wprod_kernel<<<dim3(16, 32), dim3(32, 8)>>>(Ws, Wn, Wc);
    beff_kernel<<<512, 256>>>(bs, bn, bc, Wc);
    gemm1_kernel<<<dim3(2, 64), 256, G1_SMEM>>>(adj);
    agg_split_kernel<<<4096, 256>>>();
    gemm_final_kernel<<<dim3(2, 64), 256, GF_SMEM>>>(out);
}